// round 15
// baseline (speedup 1.0000x reference)
#include <cuda_runtime.h>
#include <cuda_fp16.h>
#include <math_constants.h>
#include <cstdint>

// ---------------------------------------------------------------------------
// att = softmax( MLP3(concat(node1, u_rep)) ), N = 200000, d = 128.
// R14: 2 CTAs/SM for latency hiding (independent CTAs interleave phases).
//   - __launch_bounds__(256, 2); logits moved to smem to fit 128 regs
//   - pure fp16 mma (R13), conflict-free STS.128 staging (R11)
// ---------------------------------------------------------------------------

#define EMB     128
#define TILE    128
#define LMAX    8
#define GMAX    512
#define THREADS 256

// ---- smem layout (bytes) ----
#define OFF_W1   0        // 32KB: W1 frag-packed fp16, 8B/frag = [bh0 bh1]
#define OFF_W2   32768    // 32KB
#define OFF_AH   65536    // 32KB (fp16 A fragments, 16B/frag)
#define OFF_CVEC 98304
#define OFF_B2   98816
#define OFF_W3   99328
#define OFF_PART 99840    // 1KB
#define OFF_RED  100864   // 32B
#define OFF_LG   100896   // 4KB (LMAX x 128 logits)
#define SMEM_TOTAL 104992

// ---------------- device scratch ----------------
__device__ float        g_ctamax[GMAX];
__device__ float        g_ctasum[GMAX];
__device__ unsigned int g_bar;
__device__ unsigned int g_done;

__device__ __forceinline__ uint32_t h2u(__half2 h) {
    return *reinterpret_cast<uint32_t*>(&h);
}

// mma.sync m16n8k16 fp16, fp32 accumulate in place (sm_80+ PTX)
__device__ __forceinline__ void mma_f16(float* c, const uint32_t* a,
                                        uint32_t b0, uint32_t b1) {
    asm volatile("mma.sync.aligned.m16n8k16.row.col.f32.f16.f16.f32 "
        "{%0,%1,%2,%3}, {%4,%5,%6,%7}, {%8,%9}, {%0,%1,%2,%3};"
        : "+f"(c[0]), "+f"(c[1]), "+f"(c[2]), "+f"(c[3])
        : "r"(a[0]), "r"(a[1]), "r"(a[2]), "r"(a[3]), "r"(b0), "r"(b1));
}

// Weight fragment address (byte offset), 8B per fragment.
__device__ __forceinline__ int widx(int n, int k) {
    int key = (((n >> 3) * 8 + (k >> 4)) * 32 + (n & 7) * 4 + ((k >> 1) & 3));
    int sub = ((k >> 3) & 1) * 2 + (k & 1);
    return key * 8 + sub * 2;
}

// ---------------------------------------------------------------------------
// One 128x128x128 layer slice: acc += Ah*Bh  (pure fp16)
// ---------------------------------------------------------------------------
__device__ __forceinline__ void run_layer(char* smc, int offW,
                                          float acc[2][8][4],
                                          int warpM, int warpN, int lane)
{
    #pragma unroll
    for (int ks = 0; ks < 8; ks++) {
        uint4 ah[2];
        #pragma unroll
        for (int mt = 0; mt < 2; mt++) {
            int mta  = warpM * 2 + mt;
            int aoff = ((mta * 8 + ks) * 32 + lane) * 16;
            ah[mt] = *(const uint4*)(smc + OFF_AH + aoff);
        }
        #pragma unroll
        for (int jb = 0; jb < 2; jb++) {
            uint2 b[4];
            #pragma unroll
            for (int j4 = 0; j4 < 4; j4++) {
                int ntg  = warpN * 8 + jb * 4 + j4;
                int boff = ((ntg * 8 + ks) * 32 + lane) * 8;
                b[j4] = *(const uint2*)(smc + offW + boff);
            }
            #pragma unroll
            for (int j4 = 0; j4 < 4; j4++)
                mma_f16(acc[0][jb * 4 + j4], (const uint32_t*)&ah[0], b[j4].x, b[j4].y);
            #pragma unroll
            for (int j4 = 0; j4 < 4; j4++)
                mma_f16(acc[1][jb * 4 + j4], (const uint32_t*)&ah[1], b[j4].x, b[j4].y);
        }
    }
}

// ---------------------------------------------------------------------------
__global__ __launch_bounds__(THREADS, 2)
void k_fused(const float* __restrict__ node1, const float* __restrict__ u_rep,
             const float* __restrict__ W1, const float* __restrict__ b1,
             const float* __restrict__ W2, const float* __restrict__ b2g,
             const float* __restrict__ w3g, const float* __restrict__ b3g,
             float* __restrict__ out, int N, int ntiles)
{
    extern __shared__ char smc[];
    const int tid   = threadIdx.x;
    const int wid   = tid >> 5;
    const int lane  = tid & 31;
    const int warpM = wid & 3;       // 4-way M split (32 rows each)
    const int warpN = wid >> 2;      // 2-way N split (64 cols each)
    const int g     = lane >> 2;
    const int t     = lane & 3;
    const int bid   = blockIdx.x;
    const unsigned G = gridDim.x;

    float* s_cvec = (float*)(smc + OFF_CVEC);
    float* s_b2   = (float*)(smc + OFF_B2);
    float* s_w3   = (float*)(smc + OFF_W3);
    float* s_part = (float*)(smc + OFF_PART);
    float* s_red  = (float*)(smc + OFF_RED);
    float* s_lg   = (float*)(smc + OFF_LG);

    // ---- in-kernel weight conversion (fp16), fragment-packed ----
    for (int i = tid; i < EMB * EMB; i += THREADS) {
        int n = i >> 7, k = i & 127;
        int off = widx(n, k);
        *(__half*)(smc + OFF_W1 + off) = __float2half_rn(W1[n * 256 + k]);
        *(__half*)(smc + OFF_W2 + off) = __float2half_rn(W2[n * 128 + k]);
    }
    // cvec = u_rep @ W1b^T + b1 (fp32, exact path)
    if (tid < 128) {
        float acc = b1[tid];
        const float* w = W1 + tid * 256 + 128;
        #pragma unroll 8
        for (int kk = 0; kk < 128; kk++) acc += u_rep[kk] * w[kk];
        s_cvec[tid] = acc;
        s_b2[tid]   = b2g[tid];
        s_w3[tid]   = w3g[tid];
    }
    __syncthreads();

    const float fb3 = b3g[0];
    const int nt = (ntiles > bid) ? (ntiles - 1 - bid) / (int)G + 1 : 0;
    float runmax = -CUDART_INF_F;

    for (int kt = 0; kt < nt; kt++) {
        const int tile = bid + kt * (int)G;
        const int base = tile * TILE;

        // ---- stage: assemble fp16 A-fragments, conflict-free STS.128 ----
        {
            const int r0 = base + wid * 16 + g;      // half=0 row
            const int r1 = r0 + 8;                   // half=1 row
            const float2* p0 = (const float2*)(node1 + (size_t)r0 * 128) + t;
            const float2* p1 = (const float2*)(node1 + (size_t)r1 * 128) + t;
            const bool ok0 = (r0 < N), ok1 = (r1 < N);
            const float2 z = make_float2(0.f, 0.f);
            #pragma unroll
            for (int ks = 0; ks < 8; ks++) {
                float2 d00 = ok0 ? p0[ks * 8]     : z;   // half0, khi0
                float2 d01 = ok0 ? p0[ks * 8 + 4] : z;   // half0, khi1
                float2 d10 = ok1 ? p1[ks * 8]     : z;   // half1, khi0
                float2 d11 = ok1 ? p1[ks * 8 + 4] : z;   // half1, khi1
                uint4 H;
                H.x = h2u(__floats2half2_rn(d00.x, d00.y));  // khi0,half0
                H.y = h2u(__floats2half2_rn(d10.x, d10.y));  // khi0,half1
                H.z = h2u(__floats2half2_rn(d01.x, d01.y));  // khi1,half0
                H.w = h2u(__floats2half2_rn(d11.x, d11.y));  // khi1,half1
                int addr = ((wid * 8 + ks) * 32 + lane) * 16;
                *(uint4*)(smc + OFF_AH + addr) = H;
            }
        }
        __syncthreads();

        // ---- layer 1 ----
        float acc[2][8][4];
        #pragma unroll
        for (int mt = 0; mt < 2; mt++)
            #pragma unroll
            for (int j = 0; j < 8; j++)
                #pragma unroll
                for (int e = 0; e < 4; e++) acc[mt][j][e] = 0.f;

        run_layer(smc, OFF_W1, acc, warpM, warpN, lane);
        __syncthreads();                 // A consumed; may be rewritten

        // ---- epilogue 1: relu(C + cvec) -> fp16 fragments, STS.128 ----
        #pragma unroll
        for (int mt = 0; mt < 2; mt++) {
            int mta = warpM * 2 + mt;
            #pragma unroll
            for (int jp = 0; jp < 4; jp++) {
                int j0 = 2 * jp, j1 = 2 * jp + 1;
                int c00 = (warpN * 8 + j0) * 8 + t * 2;   // cols of j0 (khi=0)
                int c10 = (warpN * 8 + j1) * 8 + t * 2;   // cols of j1 (khi=1)
                float* ca = acc[mt][j0];
                float* cb = acc[mt][j1];
                float va0 = fmaxf(ca[0] + s_cvec[c00],     0.f);
                float va1 = fmaxf(ca[1] + s_cvec[c00 + 1], 0.f);
                float va2 = fmaxf(ca[2] + s_cvec[c00],     0.f);
                float va3 = fmaxf(ca[3] + s_cvec[c00 + 1], 0.f);
                float vb0 = fmaxf(cb[0] + s_cvec[c10],     0.f);
                float vb1 = fmaxf(cb[1] + s_cvec[c10 + 1], 0.f);
                float vb2 = fmaxf(cb[2] + s_cvec[c10],     0.f);
                float vb3 = fmaxf(cb[3] + s_cvec[c10 + 1], 0.f);
                uint4 H;
                H.x = h2u(__floats2half2_rn(va0, va1));   // khi0 (j0), row g
                H.y = h2u(__floats2half2_rn(va2, va3));   // khi0, row g+8
                H.z = h2u(__floats2half2_rn(vb0, vb1));   // khi1 (j1), row g
                H.w = h2u(__floats2half2_rn(vb2, vb3));   // khi1, row g+8
                int key  = mta * 8 + warpN * 4 + jp;
                int addr = (key * 32 + lane) * 16;
                *(uint4*)(smc + OFF_AH + addr) = H;
                ca[0] = ca[1] = ca[2] = ca[3] = 0.f;
                cb[0] = cb[1] = cb[2] = cb[3] = 0.f;
            }
        }
        __syncthreads();

        // ---- layer 2 ----
        run_layer(smc, OFF_W2, acc, warpM, warpN, lane);

        // ---- epilogue 2: relu(C + b2) dot w3 -> per-row partials ----
        float sp[2][2] = {{0.f, 0.f}, {0.f, 0.f}};   // [mt][half]
        #pragma unroll
        for (int mt = 0; mt < 2; mt++) {
            #pragma unroll
            for (int j = 0; j < 8; j++) {
                int col0 = (warpN * 8 + j) * 8 + t * 2;
                float* c = acc[mt][j];
                float w0 = s_w3[col0], w1 = s_w3[col0 + 1];
                float bb0 = s_b2[col0], bb1 = s_b2[col0 + 1];
                sp[mt][0] += fmaxf(c[0] + bb0, 0.f) * w0
                           + fmaxf(c[1] + bb1, 0.f) * w1;
                sp[mt][1] += fmaxf(c[2] + bb0, 0.f) * w0
                           + fmaxf(c[3] + bb1, 0.f) * w1;
            }
        }
        #pragma unroll
        for (int off = 1; off < 4; off <<= 1) {
            #pragma unroll
            for (int mt = 0; mt < 2; mt++) {
                sp[mt][0] += __shfl_xor_sync(0xffffffffu, sp[mt][0], off);
                sp[mt][1] += __shfl_xor_sync(0xffffffffu, sp[mt][1], off);
            }
        }
        if (t == 0) {
            #pragma unroll
            for (int mt = 0; mt < 2; mt++) {
                int rbase = warpM * 32 + mt * 16;
                s_part[warpN * 128 + rbase + g]     = sp[mt][0];
                s_part[warpN * 128 + rbase + 8 + g] = sp[mt][1];
            }
        }
        __syncthreads();

        if (tid < 128) {
            int gr = base + tid;
            float v = s_part[tid] + s_part[128 + tid] + fb3;
            s_lg[kt * 128 + tid] = v;
            if (gr < N) runmax = fmaxf(runmax, v);
        }
        __syncthreads();
    }

    // ---- phase-1 end: per-CTA max ----
    float m = runmax;
    #pragma unroll
    for (int s = 16; s > 0; s >>= 1) m = fmaxf(m, __shfl_xor_sync(0xffffffffu, m, s));
    if (lane == 0) s_red[wid] = m;
    __syncthreads();
    if (tid == 0) {
        float mx = s_red[0];
        #pragma unroll
        for (int i = 1; i < 8; i++) mx = fmaxf(mx, s_red[i]);
        g_ctamax[bid] = mx;
        __threadfence();
        atomicAdd(&g_bar, 1u);
        while (atomicAdd(&g_bar, 0u) < G) __nanosleep(64);
        __threadfence();
    }
    __syncthreads();

    // ---- phase 2: global max (deterministic serial), exp, per-CTA sum ----
    float gmax = g_ctamax[0];
    for (unsigned i = 1; i < G; i++) gmax = fmaxf(gmax, g_ctamax[i]);

    float psum = 0.f;
    if (tid < 128) {
        for (int kt = 0; kt < nt; kt++) {
            int gr = (bid + kt * (int)G) * TILE + tid;
            if (gr < N) {
                float e = __expf(s_lg[kt * 128 + tid] - gmax);
                s_lg[kt * 128 + tid] = e;
                psum += e;
            }
        }
    }
    #pragma unroll
    for (int s = 16; s > 0; s >>= 1) psum += __shfl_xor_sync(0xffffffffu, psum, s);
    if (lane == 0) s_red[wid] = psum;
    __syncthreads();
    if (tid == 0) {
        float sm = 0.f;
        #pragma unroll
        for (int i = 0; i < 8; i++) sm += s_red[i];
        g_ctasum[bid] = sm;
        __threadfence();
        atomicAdd(&g_bar, 1u);
        while (atomicAdd(&g_bar, 0u) < 2u * G) __nanosleep(64);
        __threadfence();
    }
    __syncthreads();

    // ---- phase 3: total sum (deterministic serial), normalize, write ----
    float tot = 0.f;
    for (unsigned i = 0; i < G; i++) tot += g_ctasum[i];
    const float inv = 1.f / tot;

    if (tid < 128) {
        for (int kt = 0; kt < nt; kt++) {
            int gr = (bid + kt * (int)G) * TILE + tid;
            if (gr < N) out[gr] = s_lg[kt * 128 + tid] * inv;
        }
    }

    // ---- reset barrier state for next graph replay ----
    __syncthreads();
    if (tid == 0) {
        unsigned d = atomicAdd(&g_done, 1u);
        if (d == G - 1u) {
            atomicExch(&g_bar, 0u);
            atomicExch(&g_done, 0u);
            __threadfence();
        }
    }
}

// ---------------------------------------------------------------------------
extern "C" void kernel_launch(void* const* d_in, const int* in_sizes, int n_in,
                              void* d_out, int out_size)
{
    const float* node1 = (const float*)d_in[0];
    const float* u_rep = (const float*)d_in[1];

    // inputs: node1, u_rep, [num_neighs], W1, b1, W2, b2, W3, b3
    int wi = (n_in >= 9) ? 2 + (n_in - 8) : 2;
    if (in_sizes[wi] != 128 * 256) {
        for (int i = 2; i + 5 < n_in; i++)
            if (in_sizes[i] == 128 * 256) { wi = i; break; }
    }
    const float* W1 = (const float*)d_in[wi + 0];
    const float* b1 = (const float*)d_in[wi + 1];
    const float* W2 = (const float*)d_in[wi + 2];
    const float* b2 = (const float*)d_in[wi + 3];
    const float* W3 = (const float*)d_in[wi + 4];
    const float* b3 = (const float*)d_in[wi + 5];
    float* out = (float*)d_out;

    const int N      = in_sizes[0] / EMB;
    const int ntiles = (N + TILE - 1) / TILE;

    int nsm = 0;
    cudaDeviceGetAttribute(&nsm, cudaDevAttrMultiProcessorCount, 0);
    if (nsm <= 0) nsm = 148;
    int grid = 2 * nsm;                          // 2 CTAs/SM
    if (grid > ntiles) grid = ntiles;
    if (grid > GMAX) grid = GMAX;
    // ensure tiles per CTA fits LMAX
    int mingrid = (ntiles + LMAX - 1) / LMAX;
    if (grid < mingrid) grid = mingrid;

    cudaFuncSetAttribute(k_fused, cudaFuncAttributeMaxDynamicSharedMemorySize,
                         SMEM_TOTAL);
    k_fused<<<grid, THREADS, SMEM_TOTAL>>>(node1, u_rep, W1, b1, W2, b2, W3, b3,
                                           out, N, ntiles);
}

// round 16
// speedup vs baseline: 1.1818x; 1.1818x over previous
#include <cuda_runtime.h>
#include <cuda_fp16.h>
#include <math_constants.h>
#include <cstdint>

// ---------------------------------------------------------------------------
// att = softmax( MLP3(concat(node1, u_rep)) ), N = 200000, d = 128.
// R15: software-pipelined tile loop.
//   - A double-buffered (A0/A1); h1 in its own buffer -> WAR syncs removed
//   - 3 __syncthreads per tile (was 5); staging LDG+STS overlapped w/ compute
//   - pure fp16 mma (R13), conflict-free STS.128 fragments (R11)
// 1 CTA/SM, 256 threads, 4Mx2N warps, fused softmax w/ grid barrier.
// ---------------------------------------------------------------------------

#define EMB     128
#define TILE    128
#define LMAX    16
#define GMAX    256
#define THREADS 256

// ---- smem layout (bytes) ----
#define OFF_W1   0        // 32KB fp16 frags, 8B/frag
#define OFF_W2   32768    // 32KB
#define OFF_A0   65536    // 32KB fp16 A fragments (buffer 0)
#define OFF_A1   98304    // 32KB (buffer 1)
#define OFF_H1   131072   // 32KB h1 fragments
#define OFF_CVEC 163840
#define OFF_B2   164352
#define OFF_W3   164864
#define OFF_PART 165376   // 1KB
#define OFF_RED  166400   // 32B
#define SMEM_TOTAL 166432

// ---------------- device scratch ----------------
__device__ float        g_ctamax[GMAX];
__device__ float        g_ctasum[GMAX];
__device__ unsigned int g_bar;
__device__ unsigned int g_done;

__device__ __forceinline__ uint32_t h2u(__half2 h) {
    return *reinterpret_cast<uint32_t*>(&h);
}

// mma.sync m16n8k16 fp16, fp32 accumulate in place (sm_80+ PTX)
__device__ __forceinline__ void mma_f16(float* c, const uint32_t* a,
                                        uint32_t b0, uint32_t b1) {
    asm volatile("mma.sync.aligned.m16n8k16.row.col.f32.f16.f16.f32 "
        "{%0,%1,%2,%3}, {%4,%5,%6,%7}, {%8,%9}, {%0,%1,%2,%3};"
        : "+f"(c[0]), "+f"(c[1]), "+f"(c[2]), "+f"(c[3])
        : "r"(a[0]), "r"(a[1]), "r"(a[2]), "r"(a[3]), "r"(b0), "r"(b1));
}

// Weight fragment address (byte offset), 8B per fragment.
__device__ __forceinline__ int widx(int n, int k) {
    int key = (((n >> 3) * 8 + (k >> 4)) * 32 + (n & 7) * 4 + ((k >> 1) & 3));
    int sub = ((k >> 3) & 1) * 2 + (k & 1);
    return key * 8 + sub * 2;
}

// ---------------------------------------------------------------------------
// One 128x128x128 layer slice: acc += Ah*Bh  (pure fp16)
// ---------------------------------------------------------------------------
__device__ __forceinline__ void run_layer(char* smc, int offA, int offW,
                                          float acc[2][8][4],
                                          int warpM, int warpN, int lane)
{
    #pragma unroll
    for (int ks = 0; ks < 8; ks++) {
        uint4 ah[2];
        #pragma unroll
        for (int mt = 0; mt < 2; mt++) {
            int mta  = warpM * 2 + mt;
            int aoff = ((mta * 8 + ks) * 32 + lane) * 16;
            ah[mt] = *(const uint4*)(smc + offA + aoff);
        }
        #pragma unroll
        for (int jb = 0; jb < 2; jb++) {
            uint2 b[4];
            #pragma unroll
            for (int j4 = 0; j4 < 4; j4++) {
                int ntg  = warpN * 8 + jb * 4 + j4;
                int boff = ((ntg * 8 + ks) * 32 + lane) * 8;
                b[j4] = *(const uint2*)(smc + offW + boff);
            }
            #pragma unroll
            for (int j4 = 0; j4 < 4; j4++)
                mma_f16(acc[0][jb * 4 + j4], (const uint32_t*)&ah[0], b[j4].x, b[j4].y);
            #pragma unroll
            for (int j4 = 0; j4 < 4; j4++)
                mma_f16(acc[1][jb * 4 + j4], (const uint32_t*)&ah[1], b[j4].x, b[j4].y);
        }
    }
}

// Load one tile's rows for this thread (rows wid*16+g, +8) and convert to
// packed fp16 fragment words: out H[ks] = {khi0half0, khi0half1, khi1half0, khi1half1}
__device__ __forceinline__ void load_convert(const float* __restrict__ node1,
                                             int base, int N, int wid, int g,
                                             int t, uint4 H[8])
{
    const int r0 = base + wid * 16 + g;
    const int r1 = r0 + 8;
    const float2* p0 = (const float2*)(node1 + (size_t)r0 * 128) + t;
    const float2* p1 = (const float2*)(node1 + (size_t)r1 * 128) + t;
    const bool ok0 = (base >= 0) && (r0 < N);
    const bool ok1 = (base >= 0) && (r1 < N);
    const float2 z = make_float2(0.f, 0.f);
    #pragma unroll
    for (int ks = 0; ks < 8; ks++) {
        float2 d00 = ok0 ? p0[ks * 8]     : z;   // half0, khi0
        float2 d01 = ok0 ? p0[ks * 8 + 4] : z;   // half0, khi1
        float2 d10 = ok1 ? p1[ks * 8]     : z;   // half1, khi0
        float2 d11 = ok1 ? p1[ks * 8 + 4] : z;   // half1, khi1
        H[ks].x = h2u(__floats2half2_rn(d00.x, d00.y));
        H[ks].y = h2u(__floats2half2_rn(d10.x, d10.y));
        H[ks].z = h2u(__floats2half2_rn(d01.x, d01.y));
        H[ks].w = h2u(__floats2half2_rn(d11.x, d11.y));
    }
}

__device__ __forceinline__ void store_frags(char* smc, int offA, int wid,
                                            int lane, const uint4 H[8])
{
    #pragma unroll
    for (int ks = 0; ks < 8; ks++) {
        int addr = ((wid * 8 + ks) * 32 + lane) * 16;
        *(uint4*)(smc + offA + addr) = H[ks];
    }
}

// ---------------------------------------------------------------------------
__global__ __launch_bounds__(THREADS, 1)
void k_fused(const float* __restrict__ node1, const float* __restrict__ u_rep,
             const float* __restrict__ W1, const float* __restrict__ b1,
             const float* __restrict__ W2, const float* __restrict__ b2g,
             const float* __restrict__ w3g, const float* __restrict__ b3g,
             float* __restrict__ out, int N, int ntiles)
{
    extern __shared__ char smc[];
    const int tid   = threadIdx.x;
    const int wid   = tid >> 5;
    const int lane  = tid & 31;
    const int warpM = wid & 3;       // 4-way M split (32 rows each)
    const int warpN = wid >> 2;      // 2-way N split (64 cols each)
    const int g     = lane >> 2;
    const int t     = lane & 3;
    const int bid   = blockIdx.x;
    const unsigned G = gridDim.x;

    float* s_cvec = (float*)(smc + OFF_CVEC);
    float* s_b2   = (float*)(smc + OFF_B2);
    float* s_w3   = (float*)(smc + OFF_W3);
    float* s_part = (float*)(smc + OFF_PART);
    float* s_red  = (float*)(smc + OFF_RED);

    // ---- in-kernel weight conversion (fp16), fragment-packed ----
    for (int i = tid; i < EMB * EMB; i += THREADS) {
        int n = i >> 7, k = i & 127;
        int off = widx(n, k);
        *(__half*)(smc + OFF_W1 + off) = __float2half_rn(W1[n * 256 + k]);
        *(__half*)(smc + OFF_W2 + off) = __float2half_rn(W2[n * 128 + k]);
    }
    // cvec = u_rep @ W1b^T + b1 (fp32, exact path)
    if (tid < 128) {
        float acc = b1[tid];
        const float* w = W1 + tid * 256 + 128;
        #pragma unroll 8
        for (int kk = 0; kk < 128; kk++) acc += u_rep[kk] * w[kk];
        s_cvec[tid] = acc;
        s_b2[tid]   = b2g[tid];
        s_w3[tid]   = w3g[tid];
    }

    const float fb3 = b3g[0];
    const int nt = (ntiles > bid) ? (ntiles - 1 - bid) / (int)G + 1 : 0;
    float lg[LMAX];
    float runmax = -CUDART_INF_F;

    // ---- preloop: stage tile 0 into A0 ----
    {
        uint4 H[8];
        load_convert(node1, (0 < nt) ? bid * TILE : -1, N, wid, g, t, H);
        store_frags(smc, OFF_A0, wid, lane, H);
    }
    __syncthreads();                     // weights + cvec + A0 ready

    for (int kt = 0; kt < nt; kt++) {
        const int base  = (bid + (size_t)0 + kt * (int)G) * TILE;
        const int offAc = (kt & 1) ? OFF_A1 : OFF_A0;
        const int offAn = (kt & 1) ? OFF_A0 : OFF_A1;

        // ---- layer 1 (A[cur] x W1) ----
        float acc[2][8][4];
        #pragma unroll
        for (int mt = 0; mt < 2; mt++)
            #pragma unroll
            for (int j = 0; j < 8; j++)
                #pragma unroll
                for (int e = 0; e < 4; e++) acc[mt][j][e] = 0.f;

        run_layer(smc, offAc, OFF_W1, acc, warpM, warpN, lane);

        // issue next tile's LDGs + convert now; latency hides under epi1+layer2
        uint4 Hn[8];
        {
            int tile2 = bid + (kt + 1) * (int)G;
            load_convert(node1, (tile2 < ntiles) ? tile2 * TILE : -1,
                         N, wid, g, t, Hn);
        }

        // ---- epilogue 1: relu(C + cvec) -> fp16 fragments into H1 ----
        // (no sync needed: H1's last readers finished before this iteration)
        #pragma unroll
        for (int mt = 0; mt < 2; mt++) {
            int mta = warpM * 2 + mt;
            #pragma unroll
            for (int jp = 0; jp < 4; jp++) {
                int j0 = 2 * jp, j1 = 2 * jp + 1;
                int c00 = (warpN * 8 + j0) * 8 + t * 2;   // cols of j0 (khi=0)
                int c10 = (warpN * 8 + j1) * 8 + t * 2;   // cols of j1 (khi=1)
                float* ca = acc[mt][j0];
                float* cb = acc[mt][j1];
                float va0 = fmaxf(ca[0] + s_cvec[c00],     0.f);
                float va1 = fmaxf(ca[1] + s_cvec[c00 + 1], 0.f);
                float va2 = fmaxf(ca[2] + s_cvec[c00],     0.f);
                float va3 = fmaxf(ca[3] + s_cvec[c00 + 1], 0.f);
                float vb0 = fmaxf(cb[0] + s_cvec[c10],     0.f);
                float vb1 = fmaxf(cb[1] + s_cvec[c10 + 1], 0.f);
                float vb2 = fmaxf(cb[2] + s_cvec[c10],     0.f);
                float vb3 = fmaxf(cb[3] + s_cvec[c10 + 1], 0.f);
                uint4 H;
                H.x = h2u(__floats2half2_rn(va0, va1));   // khi0 (j0), row g
                H.y = h2u(__floats2half2_rn(va2, va3));   // khi0, row g+8
                H.z = h2u(__floats2half2_rn(vb0, vb1));   // khi1 (j1), row g
                H.w = h2u(__floats2half2_rn(vb2, vb3));   // khi1, row g+8
                int key  = mta * 8 + warpN * 4 + jp;
                int addr = (key * 32 + lane) * 16;
                *(uint4*)(smc + OFF_H1 + addr) = H;
                ca[0] = ca[1] = ca[2] = ca[3] = 0.f;
                cb[0] = cb[1] = cb[2] = cb[3] = 0.f;
            }
        }
        __syncthreads();                 // (b) H1 complete

        // ---- layer 2 (H1 x W2) ----
        run_layer(smc, OFF_H1, OFF_W2, acc, warpM, warpN, lane);

        // stage next tile into the other A buffer (consumed after next sync)
        store_frags(smc, offAn, wid, lane, Hn);

        // ---- epilogue 2: relu(C + b2) dot w3 -> per-row partials ----
        float sp[2][2] = {{0.f, 0.f}, {0.f, 0.f}};   // [mt][half]
        #pragma unroll
        for (int mt = 0; mt < 2; mt++) {
            #pragma unroll
            for (int j = 0; j < 8; j++) {
                int col0 = (warpN * 8 + j) * 8 + t * 2;
                float* c = acc[mt][j];
                float w0 = s_w3[col0], w1 = s_w3[col0 + 1];
                float bb0 = s_b2[col0], bb1 = s_b2[col0 + 1];
                sp[mt][0] += fmaxf(c[0] + bb0, 0.f) * w0
                           + fmaxf(c[1] + bb1, 0.f) * w1;
                sp[mt][1] += fmaxf(c[2] + bb0, 0.f) * w0
                           + fmaxf(c[3] + bb1, 0.f) * w1;
            }
        }
        #pragma unroll
        for (int off = 1; off < 4; off <<= 1) {
            #pragma unroll
            for (int mt = 0; mt < 2; mt++) {
                sp[mt][0] += __shfl_xor_sync(0xffffffffu, sp[mt][0], off);
                sp[mt][1] += __shfl_xor_sync(0xffffffffu, sp[mt][1], off);
            }
        }
        if (t == 0) {
            #pragma unroll
            for (int mt = 0; mt < 2; mt++) {
                int rbase = warpM * 32 + mt * 16;
                s_part[warpN * 128 + rbase + g]     = sp[mt][0];
                s_part[warpN * 128 + rbase + 8 + g] = sp[mt][1];
            }
        }
        __syncthreads();                 // (c) s_part + A[nxt] complete

        if (tid < 128) {
            int gr = base + tid;
            float v = s_part[tid] + s_part[128 + tid] + fb3;
            lg[kt] = v;
            if (gr < N) runmax = fmaxf(runmax, v);
        }
        __syncthreads();                 // (a) s_part free; A[nxt] ready
    }

    // ---- phase-1 end: per-CTA max ----
    float m = runmax;
    #pragma unroll
    for (int s = 16; s > 0; s >>= 1) m = fmaxf(m, __shfl_xor_sync(0xffffffffu, m, s));
    if (lane == 0) s_red[wid] = m;
    __syncthreads();
    if (tid == 0) {
        float mx = s_red[0];
        #pragma unroll
        for (int i = 1; i < 8; i++) mx = fmaxf(mx, s_red[i]);
        g_ctamax[bid] = mx;
        __threadfence();
        atomicAdd(&g_bar, 1u);
        while (atomicAdd(&g_bar, 0u) < G) __nanosleep(64);
        __threadfence();
    }
    __syncthreads();

    // ---- phase 2: global max (deterministic serial), exp, per-CTA sum ----
    float gmax = g_ctamax[0];
    for (unsigned i = 1; i < G; i++) gmax = fmaxf(gmax, g_ctamax[i]);

    float psum = 0.f;
    if (tid < 128) {
        for (int kt = 0; kt < nt; kt++) {
            int gr = (bid + kt * (int)G) * TILE + tid;
            if (gr < N) {
                float e = __expf(lg[kt] - gmax);
                lg[kt] = e;
                psum += e;
            }
        }
    }
    #pragma unroll
    for (int s = 16; s > 0; s >>= 1) psum += __shfl_xor_sync(0xffffffffu, psum, s);
    if (lane == 0) s_red[wid] = psum;
    __syncthreads();
    if (tid == 0) {
        float sm = 0.f;
        #pragma unroll
        for (int i = 0; i < 8; i++) sm += s_red[i];
        g_ctasum[bid] = sm;
        __threadfence();
        atomicAdd(&g_bar, 1u);
        while (atomicAdd(&g_bar, 0u) < 2u * G) __nanosleep(64);
        __threadfence();
    }
    __syncthreads();

    // ---- phase 3: total sum (deterministic serial), normalize, write ----
    float tot = 0.f;
    for (unsigned i = 0; i < G; i++) tot += g_ctasum[i];
    const float inv = 1.f / tot;

    if (tid < 128) {
        for (int kt = 0; kt < nt; kt++) {
            int gr = (bid + kt * (int)G) * TILE + tid;
            if (gr < N) out[gr] = lg[kt] * inv;
        }
    }

    // ---- reset barrier state for next graph replay ----
    __syncthreads();
    if (tid == 0) {
        unsigned d = atomicAdd(&g_done, 1u);
        if (d == G - 1u) {
            atomicExch(&g_bar, 0u);
            atomicExch(&g_done, 0u);
            __threadfence();
        }
    }
}

// ---------------------------------------------------------------------------
extern "C" void kernel_launch(void* const* d_in, const int* in_sizes, int n_in,
                              void* d_out, int out_size)
{
    const float* node1 = (const float*)d_in[0];
    const float* u_rep = (const float*)d_in[1];

    // inputs: node1, u_rep, [num_neighs], W1, b1, W2, b2, W3, b3
    int wi = (n_in >= 9) ? 2 + (n_in - 8) : 2;
    if (in_sizes[wi] != 128 * 256) {
        for (int i = 2; i + 5 < n_in; i++)
            if (in_sizes[i] == 128 * 256) { wi = i; break; }
    }
    const float* W1 = (const float*)d_in[wi + 0];
    const float* b1 = (const float*)d_in[wi + 1];
    const float* W2 = (const float*)d_in[wi + 2];
    const float* b2 = (const float*)d_in[wi + 3];
    const float* W3 = (const float*)d_in[wi + 4];
    const float* b3 = (const float*)d_in[wi + 5];
    float* out = (float*)d_out;

    const int N      = in_sizes[0] / EMB;
    const int ntiles = (N + TILE - 1) / TILE;

    int nsm = 0;
    cudaDeviceGetAttribute(&nsm, cudaDevAttrMultiProcessorCount, 0);
    if (nsm <= 0) nsm = 148;
    int grid = ntiles < nsm ? ntiles : nsm;
    if (grid > GMAX) grid = GMAX;

    cudaFuncSetAttribute(k_fused, cudaFuncAttributeMaxDynamicSharedMemorySize,
                         SMEM_TOTAL);
    k_fused<<<grid, THREADS, SMEM_TOTAL>>>(node1, u_rep, W1, b1, W2, b2, W3, b3,
                                           out, N, ntiles);
}